// round 2
// baseline (speedup 1.0000x reference)
#include <cuda_runtime.h>
#include <math.h>

#define NE 8
#define DIM 1024
#define DFF 4096
#define MAXN 4096
#define MAXA (2*MAXN)

// ---------------- scratch (device globals: allocation-free) ----------------
__device__ float g_X[(size_t)MAXA * DIM];     // 32 MB: expert-permuted activations
__device__ float g_H[(size_t)MAXA * DFF];     // 128 MB: hidden (post-GELU)
__device__ int   g_cnt[NE];
__device__ int   g_off[NE];
__device__ int   g_cur[NE];
__device__ int   g_tope[MAXA];                // per assignment: expert id
__device__ float g_topg[MAXA];                // per assignment: normalized gate
__device__ int   g_rowtok[MAXA];              // permuted row -> token
__device__ float g_rowgate[MAXA];             // permuted row -> gate

// ---------------- small helpers ----------------
__device__ __forceinline__ float to_tf32(float x) {
    asm("cvt.rna.tf32.f32 %0, %1;" : "=f"(x) : "f"(x));
    return x;
}

__device__ __forceinline__ void mma_tf32(float c[4], const unsigned a[4], const unsigned b[2]) {
    asm volatile(
        "mma.sync.aligned.m16n8k8.row.col.f32.tf32.tf32.f32 "
        "{%0,%1,%2,%3}, {%4,%5,%6,%7}, {%8,%9}, {%0,%1,%2,%3};\n"
        : "+f"(c[0]), "+f"(c[1]), "+f"(c[2]), "+f"(c[3])
        : "r"(a[0]), "r"(a[1]), "r"(a[2]), "r"(a[3]), "r"(b[0]), "r"(b[1]));
}

__device__ __forceinline__ float gelu_exact(float v) {
    return 0.5f * v * (1.0f + erff(v * 0.70710678118654752f));
}

// ---------------- kernel 1: reset counters ----------------
__global__ void reset_kernel() {
    if (threadIdx.x < NE) g_cnt[threadIdx.x] = 0;
}

// ---------------- kernel 2: routing (one block per token) ----------------
// CRITICAL: top-2 selection must be done on SIGMOID GATES (which saturate to
// exactly 1.0f for logits >~ 17 — common here since logit std ~= 32) with
// lowest-index tie-breaking, to match jax.lax.top_k's stable tie handling.
__global__ void route_kernel(const float* __restrict__ x,
                             const float* __restrict__ cent) {
    __shared__ float su[DIM];
    __shared__ float slog[NE];
    const int tok = blockIdx.x;
    const float* u = x + (size_t)tok * DIM;
    for (int i = threadIdx.x; i < DIM; i += blockDim.x) su[i] = u[i];
    __syncthreads();

    const int w = threadIdx.x >> 5, lane = threadIdx.x & 31;   // 8 warps = 8 experts
    const float* c = cent + (size_t)w * DIM;
    float s = 0.f;
    for (int i = lane; i < DIM; i += 32) s += su[i] * c[i];
    #pragma unroll
    for (int o = 16; o; o >>= 1) s += __shfl_xor_sync(0xffffffffu, s, o);
    if (lane == 0) slog[w] = s;
    __syncthreads();

    if (threadIdx.x == 0) {
        float gate[NE];
        #pragma unroll
        for (int e = 0; e < NE; e++) gate[e] = 1.0f / (1.0f + expf(-slog[e]));
        // top-1: strict > with ascending scan => lowest index wins ties
        int e1 = 0; float v1 = gate[0];
        #pragma unroll
        for (int e = 1; e < NE; e++) if (gate[e] > v1) { v1 = gate[e]; e1 = e; }
        // top-2 among the rest, same tie-break
        int e2 = -1; float v2 = -1.0f;
        #pragma unroll
        for (int e = 0; e < NE; e++) if (e != e1 && gate[e] > v2) { v2 = gate[e]; e2 = e; }
        float inv = 1.0f / (v1 + v2);
        g_tope[2*tok + 0] = e1;  g_topg[2*tok + 0] = v1 * inv;
        g_tope[2*tok + 1] = e2;  g_topg[2*tok + 1] = v2 * inv;
        atomicAdd(&g_cnt[e1], 1);
        atomicAdd(&g_cnt[e2], 1);
    }
}

// ---------------- kernel 3: exclusive scan over 8 counters ----------------
__global__ void scan_kernel() {
    if (threadIdx.x == 0) {
        int o = 0;
        #pragma unroll
        for (int e = 0; e < NE; e++) { g_off[e] = o; g_cur[e] = o; o += g_cnt[e]; }
    }
}

// ---------------- kernel 4: permute/gather activations (1 block per assignment) ----------------
__global__ void permute_kernel(const float* __restrict__ x) {
    __shared__ int spos;
    const int a = blockIdx.x;
    if (threadIdx.x == 0) {
        int e = g_tope[a];
        int p = atomicAdd(&g_cur[e], 1);
        g_rowtok[p]  = a >> 1;
        g_rowgate[p] = g_topg[a];
        spos = p;
    }
    __syncthreads();
    const int p = spos;
    const float4* src = (const float4*)(x + (size_t)(a >> 1) * DIM);
    float4* dst = (float4*)(g_X + (size_t)p * DIM);
    for (int i = threadIdx.x; i < DIM / 4; i += blockDim.x) dst[i] = src[i];
}

// ---------------- kernel 5: init output with gate-weighted b2 ----------------
__global__ void outinit_kernel(const float* __restrict__ b2,
                               float* __restrict__ out) {
    const int tok = blockIdx.x;
    const int e1 = g_tope[2*tok], e2 = g_tope[2*tok + 1];
    const float g1 = g_topg[2*tok], g2 = g_topg[2*tok + 1];
    const float* p1 = b2 + (size_t)e1 * DIM;
    const float* p2 = b2 + (size_t)e2 * DIM;
    float* o = out + (size_t)tok * DIM;
    for (int i = threadIdx.x; i < DIM; i += blockDim.x)
        o[i] = g1 * p1[i] + g2 * p2[i];
}

// ---------------- kernels 6/7: tf32 tiled GEMM, 128x128x32, 256 threads ----------------
// PHASE 1: H[p, :] = gelu(X[p, :] @ W1[e] + b1[e])           (KDIM=1024, NDIM=4096)
// PHASE 2: out[tok(p), :] += gate(p) * (H[p, :] @ W2[e])     (KDIM=4096, NDIM=1024)
template<int KDIM, int NDIM, int PHASE>
__global__ void __launch_bounds__(256, 2)
gemm_kernel(const float* __restrict__ Ball,
            const float* __restrict__ biasAll,
            float* __restrict__ out) {
    constexpr int BM = 128, BN = 128, BK = 32;
    __shared__ float As[BM][BK + 4];   // +4 pad: conflict-free frag reads
    __shared__ float Bs[BK][BN + 4];

    const int rtiles = gridDim.y / NE;
    const int e  = blockIdx.y / rtiles;
    const int rt = blockIdx.y % rtiles;
    const int cnt = g_cnt[e];
    if (rt * BM >= cnt) return;
    const int row0  = g_off[e] + rt * BM;
    int nrows = cnt - rt * BM; if (nrows > BM) nrows = BM;
    const int col0 = blockIdx.x * BN;

    const float* Aptr = (PHASE == 1 ? g_X : g_H) + (size_t)row0 * KDIM;
    const float* Bptr = Ball + (size_t)e * KDIM * NDIM + col0;

    const int tid  = threadIdx.x;
    const int w    = tid >> 5, lane = tid & 31;
    const int grp  = lane >> 2, qid = lane & 3;
    const int wm   = (w >> 1) * 32;    // 4 warps along M
    const int wn   = (w & 1) * 64;     // 2 warps along N

    float acc[2][8][4];
    #pragma unroll
    for (int tm = 0; tm < 2; tm++)
        #pragma unroll
        for (int tn = 0; tn < 8; tn++)
            #pragma unroll
            for (int i = 0; i < 4; i++) acc[tm][tn][i] = 0.f;

    for (int kt = 0; kt < KDIM / BK; kt++) {
        // --- load A tile (guard partial rows), convert to tf32 ---
        #pragma unroll
        for (int j = 0; j < 4; j++) {
            int v  = tid + j * 256;
            int r  = v >> 3;        // 8 float4 per row
            int c4 = v & 7;
            float4 val = make_float4(0.f, 0.f, 0.f, 0.f);
            if (r < nrows)
                val = *(const float4*)(Aptr + (size_t)r * KDIM + kt * BK + c4 * 4);
            As[r][c4*4+0] = to_tf32(val.x);
            As[r][c4*4+1] = to_tf32(val.y);
            As[r][c4*4+2] = to_tf32(val.z);
            As[r][c4*4+3] = to_tf32(val.w);
        }
        // --- load B tile ---
        #pragma unroll
        for (int j = 0; j < 4; j++) {
            int v  = tid + j * 256;
            int r  = v >> 5;        // 32 float4 per row
            int c4 = v & 31;
            float4 val = *(const float4*)(Bptr + (size_t)(kt * BK + r) * NDIM + c4 * 4);
            Bs[r][c4*4+0] = to_tf32(val.x);
            Bs[r][c4*4+1] = to_tf32(val.y);
            Bs[r][c4*4+2] = to_tf32(val.z);
            Bs[r][c4*4+3] = to_tf32(val.w);
        }
        __syncthreads();

        #pragma unroll
        for (int ks = 0; ks < 4; ks++) {
            const int k8 = ks * 8;
            unsigned af[2][4];
            #pragma unroll
            for (int tm = 0; tm < 2; tm++) {
                int r = wm + tm * 16 + grp;
                af[tm][0] = __float_as_uint(As[r    ][k8 + qid]);
                af[tm][1] = __float_as_uint(As[r + 8][k8 + qid]);
                af[tm][2] = __float_as_uint(As[r    ][k8 + qid + 4]);
                af[tm][3] = __float_as_uint(As[r + 8][k8 + qid + 4]);
            }
            unsigned bf[8][2];
            #pragma unroll
            for (int tn = 0; tn < 8; tn++) {
                int cb = wn + tn * 8 + grp;
                bf[tn][0] = __float_as_uint(Bs[k8 + qid    ][cb]);
                bf[tn][1] = __float_as_uint(Bs[k8 + qid + 4][cb]);
            }
            #pragma unroll
            for (int tm = 0; tm < 2; tm++)
                #pragma unroll
                for (int tn = 0; tn < 8; tn++)
                    mma_tf32(acc[tm][tn], af[tm], bf[tn]);
        }
        __syncthreads();
    }

    // --- epilogue ---
    if (PHASE == 1) {
        const float* bias = biasAll + (size_t)e * NDIM + col0;
        #pragma unroll
        for (int tm = 0; tm < 2; tm++) {
            #pragma unroll
            for (int half = 0; half < 2; half++) {
                int rl = wm + tm * 16 + grp + half * 8;
                if (rl < nrows) {
                    float* hrow = g_H + (size_t)(row0 + rl) * NDIM + col0;
                    #pragma unroll
                    for (int tn = 0; tn < 8; tn++) {
                        int c = wn + tn * 8 + qid * 2;
                        hrow[c    ] = gelu_exact(acc[tm][tn][half*2    ] + bias[c]);
                        hrow[c + 1] = gelu_exact(acc[tm][tn][half*2 + 1] + bias[c + 1]);
                    }
                }
            }
        }
    } else {
        #pragma unroll
        for (int tm = 0; tm < 2; tm++) {
            #pragma unroll
            for (int half = 0; half < 2; half++) {
                int rl = wm + tm * 16 + grp + half * 8;
                if (rl < nrows) {
                    int p = row0 + rl;
                    float g = g_rowgate[p];
                    float* orow = out + (size_t)g_rowtok[p] * DIM + col0;
                    #pragma unroll
                    for (int tn = 0; tn < 8; tn++) {
                        int c = wn + tn * 8 + qid * 2;
                        atomicAdd(&orow[c    ], g * acc[tm][tn][half*2    ]);
                        atomicAdd(&orow[c + 1], g * acc[tm][tn][half*2 + 1]);
                    }
                }
            }
        }
    }
}

// ---------------- launch ----------------
extern "C" void kernel_launch(void* const* d_in, const int* in_sizes, int n_in,
                              void* d_out, int out_size) {
    const float* x    = (const float*)d_in[0];
    const float* cent = (const float*)d_in[1];
    const float* W1   = (const float*)d_in[2];
    const float* b1   = (const float*)d_in[3];
    const float* W2   = (const float*)d_in[4];
    const float* b2   = (const float*)d_in[5];
    float* out = (float*)d_out;

    const int n = in_sizes[0] / DIM;   // 4096 tokens

    reset_kernel<<<1, 32>>>();
    route_kernel<<<n, 256>>>(x, cent);
    scan_kernel<<<1, 1>>>();
    permute_kernel<<<2 * n, 256>>>(x);
    outinit_kernel<<<n, 256>>>(b2, out);

    const int rtiles = (n + 127) / 128;   // per-expert cnt <= n
    dim3 grid1(DFF / 128, NE * rtiles);
    gemm_kernel<DIM, DFF, 1><<<grid1, 256>>>(W1, b1, nullptr);
    dim3 grid2(DIM / 128, NE * rtiles);
    gemm_kernel<DFF, DIM, 2><<<grid2, 256>>>(W2, nullptr, out);
}

// round 3
// speedup vs baseline: 1.1694x; 1.1694x over previous
#include <cuda_runtime.h>
#include <math.h>

#define NE 8
#define DIM 1024
#define DFF 4096
#define MAXN 4096
#define MAXA (2*MAXN)

// ---------------- scratch (device globals: allocation-free) ----------------
__device__ float g_X[(size_t)MAXA * DIM];     // 32 MB: expert-permuted activations
__device__ float g_H[(size_t)MAXA * DFF];     // 128 MB: hidden (post-GELU)
__device__ int   g_cnt[NE];
__device__ int   g_off[NE];
__device__ int   g_cur[NE];
__device__ int   g_tope[MAXA];
__device__ float g_topg[MAXA];
__device__ int   g_rowtok[MAXA];
__device__ float g_rowgate[MAXA];

// ---------------- helpers ----------------
__device__ __forceinline__ float to_tf32(float x) {
    asm("cvt.rna.tf32.f32 %0, %1;" : "=f"(x) : "f"(x));
    return x;
}

__device__ __forceinline__ void mma_tf32(float c[4], const unsigned a[4], const unsigned b[2]) {
    asm volatile(
        "mma.sync.aligned.m16n8k8.row.col.f32.tf32.tf32.f32 "
        "{%0,%1,%2,%3}, {%4,%5,%6,%7}, {%8,%9}, {%0,%1,%2,%3};\n"
        : "+f"(c[0]), "+f"(c[1]), "+f"(c[2]), "+f"(c[3])
        : "r"(a[0]), "r"(a[1]), "r"(a[2]), "r"(a[3]), "r"(b[0]), "r"(b[1]));
}

__device__ __forceinline__ float gelu_exact(float v) {
    return 0.5f * v * (1.0f + erff(v * 0.70710678118654752f));
}

__device__ __forceinline__ void cp_async16(void* sdst, const void* gsrc, bool pred) {
    unsigned saddr = (unsigned)__cvta_generic_to_shared(sdst);
    int sz = pred ? 16 : 0;
    asm volatile("cp.async.cg.shared.global [%0], [%1], 16, %2;\n"
                 :: "r"(saddr), "l"(gsrc), "r"(sz));
}
#define CP_COMMIT() asm volatile("cp.async.commit_group;\n")
#define CP_WAIT2()  asm volatile("cp.async.wait_group 2;\n")

// ---------------- kernel 1: reset ----------------
__global__ void reset_kernel() {
    if (threadIdx.x < NE) g_cnt[threadIdx.x] = 0;
}

// ---------------- kernel 2: routing ----------------
// top-2 on SIGMOID GATES (saturate to 1.0f often; logit std ~32) with
// lowest-index tie-break to match jax.lax.top_k.
__global__ void route_kernel(const float* __restrict__ x,
                             const float* __restrict__ cent) {
    __shared__ float su[DIM];
    __shared__ float slog[NE];
    const int tok = blockIdx.x;
    const float* u = x + (size_t)tok * DIM;
    for (int i = threadIdx.x; i < DIM; i += blockDim.x) su[i] = u[i];
    __syncthreads();

    const int w = threadIdx.x >> 5, lane = threadIdx.x & 31;
    const float* c = cent + (size_t)w * DIM;
    float s = 0.f;
    for (int i = lane; i < DIM; i += 32) s += su[i] * c[i];
    #pragma unroll
    for (int o = 16; o; o >>= 1) s += __shfl_xor_sync(0xffffffffu, s, o);
    if (lane == 0) slog[w] = s;
    __syncthreads();

    if (threadIdx.x == 0) {
        float gate[NE];
        #pragma unroll
        for (int e = 0; e < NE; e++) gate[e] = 1.0f / (1.0f + expf(-slog[e]));
        int e1 = 0; float v1 = gate[0];
        #pragma unroll
        for (int e = 1; e < NE; e++) if (gate[e] > v1) { v1 = gate[e]; e1 = e; }
        int e2 = -1; float v2 = -1.0f;
        #pragma unroll
        for (int e = 0; e < NE; e++) if (e != e1 && gate[e] > v2) { v2 = gate[e]; e2 = e; }
        float inv = 1.0f / (v1 + v2);
        g_tope[2*tok + 0] = e1;  g_topg[2*tok + 0] = v1 * inv;
        g_tope[2*tok + 1] = e2;  g_topg[2*tok + 1] = v2 * inv;
        atomicAdd(&g_cnt[e1], 1);
        atomicAdd(&g_cnt[e2], 1);
    }
}

// ---------------- kernel 3: scan ----------------
__global__ void scan_kernel() {
    if (threadIdx.x == 0) {
        int o = 0;
        #pragma unroll
        for (int e = 0; e < NE; e++) { g_off[e] = o; g_cur[e] = o; o += g_cnt[e]; }
    }
}

// ---------------- kernel 4: permute/gather ----------------
__global__ void permute_kernel(const float* __restrict__ x) {
    __shared__ int spos;
    const int a = blockIdx.x;
    if (threadIdx.x == 0) {
        int e = g_tope[a];
        int p = atomicAdd(&g_cur[e], 1);
        g_rowtok[p]  = a >> 1;
        g_rowgate[p] = g_topg[a];
        spos = p;
    }
    __syncthreads();
    const int p = spos;
    const float4* src = (const float4*)(x + (size_t)(a >> 1) * DIM);
    float4* dst = (float4*)(g_X + (size_t)p * DIM);
    for (int i = threadIdx.x; i < DIM / 4; i += blockDim.x) dst[i] = src[i];
}

// ---------------- kernel 5: init output with gate-weighted b2 ----------------
__global__ void outinit_kernel(const float* __restrict__ b2,
                               float* __restrict__ out) {
    const int tok = blockIdx.x;
    const int e1 = g_tope[2*tok], e2 = g_tope[2*tok + 1];
    const float g1 = g_topg[2*tok], g2 = g_topg[2*tok + 1];
    const float* p1 = b2 + (size_t)e1 * DIM;
    const float* p2 = b2 + (size_t)e2 * DIM;
    float* o = out + (size_t)tok * DIM;
    for (int i = threadIdx.x; i < DIM; i += blockDim.x)
        o[i] = g1 * p1[i] + g2 * p2[i];
}

// ---------------- GEMM: tf32 mma, 128x128x16 tiles, 4-stage cp.async ----------------
// 128 threads, 4 warps (2x2), warp tile 64x64.
// PHASE 1: H = gelu(X @ W1 + b1)     PHASE 2: out[tok] += gate * (H @ W2)
template<int KDIM, int NDIM, int PHASE>
__global__ void __launch_bounds__(128)
gemm_kernel(const float* __restrict__ Ball,
            const float* __restrict__ biasAll,
            float* __restrict__ out) {
    constexpr int BM = 128, BN = 128, BK = 16, STAGES = 4;
    constexpr int AS = 20;            // A smem row stride (floats): banks (20g+q)%32 distinct/phase
    constexpr int BS = 132;           // B smem row stride: (4q+g)%32 distinct/phase
    constexpr int ASZ = BM * AS;      // 2560 floats / stage
    constexpr int BSZ = BK * BS;      // 2112 floats / stage

    extern __shared__ float smem[];
    float* Asm = smem;                    // [STAGES][ASZ]
    float* Bsm = smem + STAGES * ASZ;     // [STAGES][BSZ]

    const int rtiles = gridDim.y / NE;
    const int e  = blockIdx.y / rtiles;
    const int rt = blockIdx.y % rtiles;
    const int cnt = g_cnt[e];
    if (rt * BM >= cnt) return;
    const int row0  = g_off[e] + rt * BM;
    int nrows = cnt - rt * BM; if (nrows > BM) nrows = BM;
    const int col0 = blockIdx.x * BN;

    const float* Aptr = (PHASE == 1 ? g_X : g_H) + (size_t)row0 * KDIM;
    const float* Bptr = Ball + (size_t)e * KDIM * NDIM + col0;

    const int tid  = threadIdx.x;
    const int w = tid >> 5, lane = tid & 31;
    const int grp = lane >> 2, qid = lane & 3;
    const int wm = (w >> 1) * 64;     // 2 warps along M
    const int wn = (w & 1) * 64;      // 2 warps along N

    const int KT = KDIM / BK;

    // loader indices (precomputed)
    int ar[4], ac4[4], bk_[4], bn4[4];
    #pragma unroll
    for (int j = 0; j < 4; j++) {
        int idx = tid + j * 128;
        ar[j]  = idx >> 2;  ac4[j] = idx & 3;    // A: 128 rows x 4 float4
        bk_[j] = idx >> 5;  bn4[j] = idx & 31;   // B: 16 rows x 32 float4
    }

    float acc[4][8][4];
    #pragma unroll
    for (int tm = 0; tm < 4; tm++)
        #pragma unroll
        for (int tn = 0; tn < 8; tn++)
            #pragma unroll
            for (int i = 0; i < 4; i++) acc[tm][tn][i] = 0.f;

    // ---- issue: copies guarded by kt < KT, commit ALWAYS (keeps group count aligned) ----
    auto issue = [&](int kt) {
        if (kt < KT) {
            int s = kt & (STAGES - 1);
            float* As = Asm + s * ASZ;
            float* Bs = Bsm + s * BSZ;
            #pragma unroll
            for (int j = 0; j < 4; j++) {
                int r = ar[j], c4 = ac4[j];
                bool ok = r < nrows;
                const float* src = Aptr + (size_t)(ok ? r : 0) * KDIM + kt * BK + c4 * 4;
                cp_async16(As + r * AS + c4 * 4, src, ok);
            }
            #pragma unroll
            for (int j = 0; j < 4; j++) {
                int k = bk_[j], n4 = bn4[j];
                const float* src = Bptr + (size_t)(kt * BK + k) * NDIM + n4 * 4;
                cp_async16(Bs + k * BS + n4 * 4, src, true);
            }
        }
        CP_COMMIT();
    };

    issue(0); issue(1); issue(2);

    const int rbase = wm + grp;

    for (int kt = 0; kt < KT; kt++) {
        CP_WAIT2();
        __syncthreads();
        issue(kt + 3);

        const int s = kt & (STAGES - 1);
        const float* As = Asm + s * ASZ;
        const float* Bs = Bsm + s * BSZ;

        #pragma unroll
        for (int ks = 0; ks < 2; ks++) {
            const int k8 = ks * 8;
            unsigned af[4][4];
            #pragma unroll
            for (int tm = 0; tm < 4; tm++) {
                int r = rbase + tm * 16;
                af[tm][0] = __float_as_uint(to_tf32(As[r * AS + k8 + qid]));
                af[tm][1] = __float_as_uint(to_tf32(As[(r + 8) * AS + k8 + qid]));
                af[tm][2] = __float_as_uint(to_tf32(As[r * AS + k8 + qid + 4]));
                af[tm][3] = __float_as_uint(to_tf32(As[(r + 8) * AS + k8 + qid + 4]));
            }
            unsigned bf[8][2];
            #pragma unroll
            for (int tn = 0; tn < 8; tn++) {
                int cb = wn + tn * 8 + grp;
                bf[tn][0] = __float_as_uint(to_tf32(Bs[(k8 + qid) * BS + cb]));
                bf[tn][1] = __float_as_uint(to_tf32(Bs[(k8 + qid + 4) * BS + cb]));
            }
            #pragma unroll
            for (int tm = 0; tm < 4; tm++)
                #pragma unroll
                for (int tn = 0; tn < 8; tn++)
                    mma_tf32(acc[tm][tn], af[tm], bf[tn]);
        }
    }

    // ---- epilogue ----
    if (PHASE == 1) {
        const float* bias = biasAll + (size_t)e * NDIM + col0;
        #pragma unroll
        for (int tm = 0; tm < 4; tm++) {
            #pragma unroll
            for (int half = 0; half < 2; half++) {
                int rl = wm + tm * 16 + grp + half * 8;
                if (rl < nrows) {
                    float* hrow = g_H + (size_t)(row0 + rl) * NDIM + col0;
                    #pragma unroll
                    for (int tn = 0; tn < 8; tn++) {
                        int c = wn + tn * 8 + qid * 2;
                        hrow[c    ] = gelu_exact(acc[tm][tn][half*2    ] + bias[c]);
                        hrow[c + 1] = gelu_exact(acc[tm][tn][half*2 + 1] + bias[c + 1]);
                    }
                }
            }
        }
    } else {
        #pragma unroll
        for (int tm = 0; tm < 4; tm++) {
            #pragma unroll
            for (int half = 0; half < 2; half++) {
                int rl = wm + tm * 16 + grp + half * 8;
                if (rl < nrows) {
                    int p = row0 + rl;
                    float g = g_rowgate[p];
                    float* orow = out + (size_t)g_rowtok[p] * DIM + col0;
                    #pragma unroll
                    for (int tn = 0; tn < 8; tn++) {
                        int c = wn + tn * 8 + qid * 2;
                        atomicAdd(&orow[c    ], g * acc[tm][tn][half*2    ]);
                        atomicAdd(&orow[c + 1], g * acc[tm][tn][half*2 + 1]);
                    }
                }
            }
        }
    }
}

// ---------------- launch ----------------
extern "C" void kernel_launch(void* const* d_in, const int* in_sizes, int n_in,
                              void* d_out, int out_size) {
    const float* x    = (const float*)d_in[0];
    const float* cent = (const float*)d_in[1];
    const float* W1   = (const float*)d_in[2];
    const float* b1   = (const float*)d_in[3];
    const float* W2   = (const float*)d_in[4];
    const float* b2   = (const float*)d_in[5];
    float* out = (float*)d_out;

    const int n = in_sizes[0] / DIM;   // 4096 tokens

    constexpr int STAGES = 4, ASZ = 128 * 20, BSZ = 16 * 132;
    const int smem_bytes = STAGES * (ASZ + BSZ) * sizeof(float);   // ~74.8 KB
    static bool attr_set = false;
    if (!attr_set) {
        cudaFuncSetAttribute(gemm_kernel<DIM, DFF, 1>,
                             cudaFuncAttributeMaxDynamicSharedMemorySize, smem_bytes);
        cudaFuncSetAttribute(gemm_kernel<DFF, DIM, 2>,
                             cudaFuncAttributeMaxDynamicSharedMemorySize, smem_bytes);
        attr_set = true;
    }

    reset_kernel<<<1, 32>>>();
    route_kernel<<<n, 256>>>(x, cent);
    scan_kernel<<<1, 1>>>();
    permute_kernel<<<2 * n, 256>>>(x);
    outinit_kernel<<<n, 256>>>(b2, out);

    const int rtiles = (n + 127) / 128;
    dim3 grid1(DFF / 128, NE * rtiles);
    gemm_kernel<DIM, DFF, 1><<<grid1, 128, smem_bytes>>>(W1, b1, nullptr);
    dim3 grid2(DIM / 128, NE * rtiles);
    gemm_kernel<DFF, DIM, 2><<<grid2, 128, smem_bytes>>>(W2, nullptr, out);
}

// round 5
// speedup vs baseline: 2.1894x; 1.8723x over previous
#include <cuda_runtime.h>
#include <cuda_fp16.h>
#include <math.h>
#include <stdint.h>

#define NE 8
#define DIM 1024
#define DFF 4096
#define MAXN 4096
#define MAXA (2*MAXN)

// ---------------- scratch (device globals: allocation-free) ----------------
__device__ __half g_Xh[(size_t)MAXA * DIM];        // 16 MB expert-permuted activations (fp16)
__device__ __half g_Hh[(size_t)MAXA * DFF];        // 64 MB hidden post-GELU (fp16)
__device__ __half g_W1h[(size_t)NE * DIM * DFF];   // 64 MB W1 fp16 [e][k][n]
__device__ __half g_W2h[(size_t)NE * DFF * DIM];   // 64 MB W2 fp16 [e][k][n]
__device__ int   g_cnt[NE];
__device__ int   g_off[NE];
__device__ int   g_cur[NE];
__device__ int   g_tope[MAXA];
__device__ float g_topg[MAXA];
__device__ int   g_rowtok[MAXA];
__device__ float g_rowgate[MAXA];

// ---------------- helpers ----------------
__device__ __forceinline__ float gelu_exact(float v) {
    return 0.5f * v * (1.0f + erff(v * 0.70710678118654752f));
}
__device__ __forceinline__ void cp16(uint32_t saddr, const void* gsrc, bool pred) {
    int sz = pred ? 16 : 0;
    asm volatile("cp.async.cg.shared.global [%0], [%1], 16, %2;\n"
                 :: "r"(saddr), "l"(gsrc), "r"(sz));
}
#define CP_COMMIT() asm volatile("cp.async.commit_group;\n")
#define CP_WAIT2()  asm volatile("cp.async.wait_group 2;\n")

__device__ __forceinline__ void ldsm_x4(unsigned r[4], uint32_t addr) {
    asm volatile("ldmatrix.sync.aligned.m8n8.x4.shared.b16 {%0,%1,%2,%3}, [%4];"
                 : "=r"(r[0]), "=r"(r[1]), "=r"(r[2]), "=r"(r[3]) : "r"(addr));
}
__device__ __forceinline__ void ldsm_x4t(unsigned r[4], uint32_t addr) {
    asm volatile("ldmatrix.sync.aligned.m8n8.x4.trans.shared.b16 {%0,%1,%2,%3}, [%4];"
                 : "=r"(r[0]), "=r"(r[1]), "=r"(r[2]), "=r"(r[3]) : "r"(addr));
}
__device__ __forceinline__ void mma_f16(float c[4], const unsigned a[4], const unsigned b[2]) {
    asm volatile(
        "mma.sync.aligned.m16n8k16.row.col.f32.f16.f16.f32 "
        "{%0,%1,%2,%3}, {%4,%5,%6,%7}, {%8,%9}, {%0,%1,%2,%3};\n"
        : "+f"(c[0]), "+f"(c[1]), "+f"(c[2]), "+f"(c[3])
        : "r"(a[0]), "r"(a[1]), "r"(a[2]), "r"(a[3]), "r"(b[0]), "r"(b[1]));
}

// ---------------- kernel 1: reset ----------------
__global__ void reset_kernel() {
    if (threadIdx.x < NE) g_cnt[threadIdx.x] = 0;
}

// ---------------- kernel 2: routing ----------------
// top-2 on SIGMOID GATES (saturate to 1.0f; logit std ~32), lowest-index
// tie-break to match jax.lax.top_k. (fp32 throughout — do not change.)
__global__ void route_kernel(const float* __restrict__ x,
                             const float* __restrict__ cent) {
    __shared__ float su[DIM];
    __shared__ float slog[NE];
    const int tok = blockIdx.x;
    const float* u = x + (size_t)tok * DIM;
    for (int i = threadIdx.x; i < DIM; i += blockDim.x) su[i] = u[i];
    __syncthreads();

    const int w = threadIdx.x >> 5, lane = threadIdx.x & 31;
    const float* c = cent + (size_t)w * DIM;
    float s = 0.f;
    for (int i = lane; i < DIM; i += 32) s += su[i] * c[i];
    #pragma unroll
    for (int o = 16; o; o >>= 1) s += __shfl_xor_sync(0xffffffffu, s, o);
    if (lane == 0) slog[w] = s;
    __syncthreads();

    if (threadIdx.x == 0) {
        float gate[NE];
        #pragma unroll
        for (int e = 0; e < NE; e++) gate[e] = 1.0f / (1.0f + expf(-slog[e]));
        int e1 = 0; float v1 = gate[0];
        #pragma unroll
        for (int e = 1; e < NE; e++) if (gate[e] > v1) { v1 = gate[e]; e1 = e; }
        int e2 = -1; float v2 = -1.0f;
        #pragma unroll
        for (int e = 0; e < NE; e++) if (e != e1 && gate[e] > v2) { v2 = gate[e]; e2 = e; }
        float inv = 1.0f / (v1 + v2);
        g_tope[2*tok + 0] = e1;  g_topg[2*tok + 0] = v1 * inv;
        g_tope[2*tok + 1] = e2;  g_topg[2*tok + 1] = v2 * inv;
        atomicAdd(&g_cnt[e1], 1);
        atomicAdd(&g_cnt[e2], 1);
    }
}

// ---------------- kernel 3: scan ----------------
__global__ void scan_kernel() {
    if (threadIdx.x == 0) {
        int o = 0;
        #pragma unroll
        for (int e = 0; e < NE; e++) { g_off[e] = o; g_cur[e] = o; o += g_cnt[e]; }
    }
}

// ---------------- kernel 4: permute/gather (fp32 -> fp16) ----------------
__global__ void permute_kernel(const float* __restrict__ x) {
    __shared__ int spos;
    const int a = blockIdx.x;
    if (threadIdx.x == 0) {
        int e = g_tope[a];
        int p = atomicAdd(&g_cur[e], 1);
        g_rowtok[p]  = a >> 1;
        g_rowgate[p] = g_topg[a];
        spos = p;
    }
    __syncthreads();
    const int p = spos;
    const float4* src = (const float4*)(x + (size_t)(a >> 1) * DIM);
    __half2* dst = (__half2*)(g_Xh + (size_t)p * DIM);
    for (int i = threadIdx.x; i < DIM / 4; i += blockDim.x) {
        float4 v = src[i];
        dst[2*i    ] = __floats2half2_rn(v.x, v.y);
        dst[2*i + 1] = __floats2half2_rn(v.z, v.w);
    }
}

// ---------------- kernel 5: init output with gate-weighted b2 ----------------
__global__ void outinit_kernel(const float* __restrict__ b2,
                               float* __restrict__ out) {
    const int tok = blockIdx.x;
    const int e1 = g_tope[2*tok], e2 = g_tope[2*tok + 1];
    const float g1 = g_topg[2*tok], g2 = g_topg[2*tok + 1];
    const float* p1 = b2 + (size_t)e1 * DIM;
    const float* p2 = b2 + (size_t)e2 * DIM;
    float* o = out + (size_t)tok * DIM;
    for (int i = threadIdx.x; i < DIM; i += blockDim.x)
        o[i] = g1 * p1[i] + g2 * p2[i];
}

// ---------------- kernel: fp32 -> fp16 weight convert (layout unchanged) ----------------
__global__ void convert_half_kernel(const float* __restrict__ src,
                                    __half* __restrict__ dst, size_t n) {
    size_t idx = ((size_t)blockIdx.x * blockDim.x + threadIdx.x) * 8;
    if (idx < n) {
        float4 v0 = *(const float4*)(src + idx);
        float4 v1 = *(const float4*)(src + idx + 4);
        __half2 h[4];
        h[0] = __floats2half2_rn(v0.x, v0.y);
        h[1] = __floats2half2_rn(v0.z, v0.w);
        h[2] = __floats2half2_rn(v1.x, v1.y);
        h[3] = __floats2half2_rn(v1.z, v1.w);
        *(uint4*)(dst + idx) = *(uint4*)h;
    }
}

// ---------------- GEMM: fp16 mma.m16n8k16, 128x128x32 tiles, 4-stage cp.async ----------------
// 128 threads, 4 warps (2x2), warp tile 64x64. ldmatrix fragment loads.
// A smem [128 rows][32 halfs], 80 B row stride. B smem [32 k-rows][128 halfs], 272 B stride.
// PHASE 1: H = gelu(Xh @ W1h + b1) -> g_Hh   PHASE 2: out[tok] += gate * (Hh @ W2h)
template<int KDIM, int NDIM, int PHASE>
__global__ void __launch_bounds__(128)
gemm_f16_kernel(const __half* __restrict__ Wh,
                const float* __restrict__ biasAll,
                float* __restrict__ out) {
    constexpr int BM = 128, BN = 128, BK = 32, STAGES = 4;
    constexpr int ASTR = 80;                    // bytes per A row (32 half + 8 pad)
    constexpr int BSTR = 272;                   // bytes per B row (128 half + 8 pad)
    constexpr int ABYTES = BM * ASTR;           // 10240
    constexpr int BBYTES = BK * BSTR;           // 8704
    constexpr int STAGE  = ABYTES + BBYTES;     // 18944 (16B aligned)

    extern __shared__ char smem_raw[];
    uint32_t sb = (uint32_t)__cvta_generic_to_shared(smem_raw);
    sb = (sb + 127u) & ~127u;

    const int rtiles = gridDim.y / NE;
    const int e  = blockIdx.y / rtiles;
    const int rt = blockIdx.y % rtiles;
    const int cnt = g_cnt[e];
    if (rt * BM >= cnt) return;
    const int row0 = g_off[e] + rt * BM;
    int nrows = cnt - rt * BM; if (nrows > BM) nrows = BM;
    const int col0 = blockIdx.x * BN;

    const __half* Aptr = (PHASE == 1 ? g_Xh : g_Hh) + (size_t)row0 * KDIM;
    const __half* Bptr = Wh + (size_t)e * KDIM * NDIM;   // [K][N] row-major

    const int tid = threadIdx.x;
    const int w = tid >> 5, lane = tid & 31;
    const int grp = lane >> 2, qid = lane & 3;
    const int wm = (w >> 1) * 64;    // 2 warps along M
    const int wn = (w & 1) * 64;     // 2 warps along N
    const int KT = KDIM / BK;

    float acc[4][8][4];
    #pragma unroll
    for (int tm = 0; tm < 4; tm++)
        #pragma unroll
        for (int tn = 0; tn < 8; tn++)
            #pragma unroll
            for (int i = 0; i < 4; i++) acc[tm][tn][i] = 0.f;

    // ---- async stage issue (commit ALWAYS to keep group counting aligned) ----
    auto issue = [&](int kt) {
        if (kt < KT) {
            const int s = kt & (STAGES - 1);
            const uint32_t ab = sb + s * STAGE;
            const uint32_t bb = ab + ABYTES;
            const int kofs = kt * BK;
            #pragma unroll
            for (int j = 0; j < 4; j++) {              // A: 512 16B chunks
                const int r = (tid >> 2) + j * 32, c = tid & 3;
                const bool ok = r < nrows;
                cp16(ab + r * ASTR + c * 16,
                     Aptr + (size_t)r * KDIM + kofs + c * 8, ok);
            }
            #pragma unroll
            for (int j = 0; j < 4; j++) {              // B: 512 16B chunks
                const int k = (tid >> 4) + j * 8, c = tid & 15;
                cp16(bb + k * BSTR + c * 16,
                     Bptr + (size_t)(kofs + k) * NDIM + col0 + c * 8, true);
            }
        }
        CP_COMMIT();
    };

    issue(0); issue(1); issue(2);

    // ldmatrix per-lane address components
    const uint32_t a_lrow = lane & 15;              // row within 16-row tile
    const uint32_t a_lcol = (lane >> 4) * 16;       // byte offset: k-halves 0/8
    const uint32_t b_lrow = lane & 15;              // k-row within 16
    const uint32_t b_lcol = (lane >> 4) * 16;       // byte offset: n 0/8

    for (int kt = 0; kt < KT; kt++) {
        CP_WAIT2();
        __syncthreads();
        issue(kt + 3);

        const int s = kt & (STAGES - 1);
        const uint32_t ab = sb + s * STAGE;
        const uint32_t bb = ab + ABYTES;

        #pragma unroll
        for (int ks = 0; ks < 2; ks++) {
            unsigned af[4][4], bf[4][4];
            #pragma unroll
            for (int mt = 0; mt < 4; mt++)
                ldsm_x4(af[mt], ab + (wm + mt * 16 + a_lrow) * ASTR + a_lcol + ks * 32);
            #pragma unroll
            for (int np = 0; np < 4; np++)
                ldsm_x4t(bf[np], bb + (ks * 16 + b_lrow) * BSTR + (wn + np * 16) * 2 + b_lcol);
            #pragma unroll
            for (int mt = 0; mt < 4; mt++)
                #pragma unroll
                for (int nt = 0; nt < 8; nt++)
                    mma_f16(acc[mt][nt], af[mt], &bf[nt >> 1][(nt & 1) * 2]);
        }
    }

    // ---- epilogue ----
    if (PHASE == 1) {
        const float* bias = biasAll + (size_t)e * NDIM + col0;
        #pragma unroll
        for (int mt = 0; mt < 4; mt++) {
            #pragma unroll
            for (int hf = 0; hf < 2; hf++) {
                const int rl = wm + mt * 16 + grp + hf * 8;
                if (rl < nrows) {
                    __half* hrow = g_Hh + (size_t)(row0 + rl) * NDIM + col0;
                    #pragma unroll
                    for (int nt = 0; nt < 8; nt++) {
                        const int c = wn + nt * 8 + qid * 2;
                        float v0 = gelu_exact(acc[mt][nt][hf*2    ] + bias[c]);
                        float v1 = gelu_exact(acc[mt][nt][hf*2 + 1] + bias[c + 1]);
                        *(__half2*)(hrow + c) = __floats2half2_rn(v0, v1);
                    }
                }
            }
        }
    } else {
        #pragma unroll
        for (int mt = 0; mt < 4; mt++) {
            #pragma unroll
            for (int hf = 0; hf < 2; hf++) {
                const int rl = wm + mt * 16 + grp + hf * 8;
                if (rl < nrows) {
                    const int p = row0 + rl;
                    const float g = g_rowgate[p];
                    float* orow = out + (size_t)g_rowtok[p] * DIM + col0;
                    #pragma unroll
                    for (int nt = 0; nt < 8; nt++) {
                        const int c = wn + nt * 8 + qid * 2;
                        atomicAdd(&orow[c    ], g * acc[mt][nt][hf*2    ]);
                        atomicAdd(&orow[c + 1], g * acc[mt][nt][hf*2 + 1]);
                    }
                }
            }
        }
    }
}

// ---------------- launch ----------------
extern "C" void kernel_launch(void* const* d_in, const int* in_sizes, int n_in,
                              void* d_out, int out_size) {
    const float* x    = (const float*)d_in[0];
    const float* cent = (const float*)d_in[1];
    const float* W1   = (const float*)d_in[2];
    const float* b1   = (const float*)d_in[3];
    const float* W2   = (const float*)d_in[4];
    const float* b2   = (const float*)d_in[5];
    float* out = (float*)d_out;

    const int n = in_sizes[0] / DIM;   // 4096 tokens

    const int smem_bytes = 4 * 18944 + 128;   // 4 stages + align slack (~74.2 KB)
    static bool attr_set = false;
    if (!attr_set) {
        cudaFuncSetAttribute(gemm_f16_kernel<DIM, DFF, 1>,
                             cudaFuncAttributeMaxDynamicSharedMemorySize, smem_bytes);
        cudaFuncSetAttribute(gemm_f16_kernel<DFF, DIM, 2>,
                             cudaFuncAttributeMaxDynamicSharedMemorySize, smem_bytes);
        attr_set = true;
    }

    __half* w1h; cudaGetSymbolAddress((void**)&w1h, g_W1h);
    __half* w2h; cudaGetSymbolAddress((void**)&w2h, g_W2h);

    reset_kernel<<<1, 32>>>();
    route_kernel<<<n, 256>>>(x, cent);
    scan_kernel<<<1, 1>>>();
    permute_kernel<<<2 * n, 256>>>(x);
    outinit_kernel<<<n, 256>>>(b2, out);

    const size_t welems = (size_t)NE * DIM * DFF;     // 33.5M
    convert_half_kernel<<<(int)(welems / 8 / 256), 256>>>(W1, w1h, welems);
    convert_half_kernel<<<(int)(welems / 8 / 256), 256>>>(W2, w2h, welems);

    const int rtiles = (n + 127) / 128;
    dim3 grid1(DFF / 128, NE * rtiles);
    gemm_f16_kernel<DIM, DFF, 1><<<grid1, 128, smem_bytes>>>(w1h, b1, nullptr);
    dim3 grid2(DIM / 128, NE * rtiles);
    gemm_f16_kernel<DFF, DIM, 2><<<grid2, 128, smem_bytes>>>(w2h, nullptr, out);
}